// round 1
// baseline (speedup 1.0000x reference)
#include <cuda_runtime.h>
#include <cuda_bf16.h>
#include <stdint.h>

// Tiling: CTA computes a 128(M) x 128(S) fp32 output tile.
// GEMM is C = A * B^T with A = x [N,512] fp32, B = gathered weight rows [S,512] fp32.
// fp32 precision recovered via 3x bf16 split linearized along K:
//   K_eff = 3*512, segments: (A_hi,B_hi), (A_lo,B_hi), (A_hi,B_lo)
#define BM    128
#define BSAMP 128
#define RS    20   // smem row stride in u32 (32 bf16 = 16 u32, +4 pad -> conflict-free frag loads)

__device__ int g_ids32;  // 1 if sample_ids buffer is actually int32

__device__ __forceinline__ uint32_t cvt_pack(float f0, float f1, int lo) {
    __nv_bfloat162 h = __floats2bfloat162_rn(f0, f1);
    if (lo) {
        float r0 = f0 - __bfloat162float(__low2bfloat16(h));
        float r1 = f1 - __bfloat162float(__high2bfloat16(h));
        h = __floats2bfloat162_rn(r0, r1);
    }
    return *reinterpret_cast<uint32_t*>(&h);
}

// Detect whether sample_ids is int64 or int32: if the buffer (viewed as int64)
// contains any value outside [0, rows), the data must be int32 (pairs of ids
// fused into one 64-bit word -> huge values). Reads only the first half of the
// element count so it stays in-bounds for the int32 case.
__global__ void detect_ids_kernel(const long long* __restrict__ ids,
                                  int nwords, long long rows) {
    __shared__ int flag;
    if (threadIdx.x == 0) flag = 0;
    __syncthreads();
    for (int i = threadIdx.x; i < nwords; i += blockDim.x) {
        long long v = ids[i];
        if (v < 0 || v >= rows) flag = 1;  // benign race, monotone
    }
    __syncthreads();
    if (threadIdx.x == 0) g_ids32 = flag;
}

__global__ __launch_bounds__(256)
void lsh_gemm_kernel(const float* __restrict__ x,
                     const float* __restrict__ w,
                     const float* __restrict__ bias,
                     const long long* __restrict__ ids,
                     float* __restrict__ out,
                     int N, int D, int S)
{
    __shared__ uint32_t sA[BM * RS];
    __shared__ uint32_t sB[BSAMP * RS];
    __shared__ long long srow[BSAMP];
    __shared__ float sbias[BSAMP];

    const int tid  = threadIdx.x;
    const int m0   = blockIdx.y * BM;
    const int s0   = blockIdx.x * BSAMP;

    // Per-tile gather metadata (once per CTA, not per K-chunk)
    if (tid < BSAMP) {
        int ids32 = g_ids32;
        long long gid = ids32 ? (long long)(((const int*)ids)[s0 + tid])
                              : ids[s0 + tid];
        srow[tid]  = gid * (long long)D;
        sbias[tid] = bias[gid];
    }

    const int lane   = tid & 31;
    const int wid    = tid >> 5;
    const int warp_m = wid >> 2;   // 0..1 -> 64 rows each
    const int warp_s = wid & 3;    // 0..3 -> 32 cols each
    const int g  = lane >> 2;      // 0..7
    const int tg = lane & 3;       // 0..3

    float acc[4][4][4];
    #pragma unroll
    for (int i = 0; i < 4; i++)
        #pragma unroll
        for (int j = 0; j < 4; j++)
            #pragma unroll
            for (int r = 0; r < 4; r++) acc[i][j][r] = 0.0f;

    __syncthreads();  // srow/sbias visible before staging

    const int chunks_per_seg = D >> 5;       // D/32
    const int nchunks = 3 * chunks_per_seg;  // K_eff / 32

    for (int c = 0; c < nchunks; ++c) {
        const int seg = c / chunks_per_seg;
        const int k0  = (c - seg * chunks_per_seg) << 5;
        const int aLo = (seg == 1);
        const int bLo = (seg == 2);

        // Stage: 128 rows x 32 fp32 each for A and B -> bf16 (hi or lo) in smem.
        // 1024 float4 per tile, 4 per thread.
        #pragma unroll
        for (int t = 0; t < 4; ++t) {
            int idx = tid + (t << 8);
            int row = idx >> 3;
            int c4  = idx & 7;
            const float4 va = *reinterpret_cast<const float4*>(
                x + (size_t)(m0 + row) * D + k0 + (c4 << 2));
            sA[row * RS + (c4 << 1)]     = cvt_pack(va.x, va.y, aLo);
            sA[row * RS + (c4 << 1) + 1] = cvt_pack(va.z, va.w, aLo);
            const float4 vb = *reinterpret_cast<const float4*>(
                w + srow[row] + k0 + (c4 << 2));
            sB[row * RS + (c4 << 1)]     = cvt_pack(vb.x, vb.y, bLo);
            sB[row * RS + (c4 << 1) + 1] = cvt_pack(vb.z, vb.w, bLo);
        }
        __syncthreads();

        // Two k16 sub-steps per 32-wide chunk
        #pragma unroll
        for (int ks = 0; ks < 2; ++ks) {
            uint32_t a[4][4];
            #pragma unroll
            for (int im = 0; im < 4; ++im) {
                int r = (warp_m << 6) + (im << 4);
                a[im][0] = sA[(r + g)     * RS + (ks << 3) + tg];
                a[im][1] = sA[(r + g + 8) * RS + (ks << 3) + tg];
                a[im][2] = sA[(r + g)     * RS + (ks << 3) + tg + 4];
                a[im][3] = sA[(r + g + 8) * RS + (ks << 3) + tg + 4];
            }
            uint32_t b[4][2];
            #pragma unroll
            for (int in = 0; in < 4; ++in) {
                int cb = (warp_s << 5) + (in << 3);
                b[in][0] = sB[(cb + g) * RS + (ks << 3) + tg];
                b[in][1] = sB[(cb + g) * RS + (ks << 3) + tg + 4];
            }
            #pragma unroll
            for (int im = 0; im < 4; ++im)
                #pragma unroll
                for (int in = 0; in < 4; ++in) {
                    asm volatile(
                        "mma.sync.aligned.m16n8k16.row.col.f32.bf16.bf16.f32 "
                        "{%0,%1,%2,%3}, {%4,%5,%6,%7}, {%8,%9}, {%0,%1,%2,%3};\n"
                        : "+f"(acc[im][in][0]), "+f"(acc[im][in][1]),
                          "+f"(acc[im][in][2]), "+f"(acc[im][in][3])
                        : "r"(a[im][0]), "r"(a[im][1]),
                          "r"(a[im][2]), "r"(a[im][3]),
                          "r"(b[in][0]), "r"(b[in][1]));
                }
        }
        __syncthreads();
    }

    // Epilogue: add bias, write fp32 with 64-bit stores.
    #pragma unroll
    for (int im = 0; im < 4; ++im) {
        int r = m0 + (warp_m << 6) + (im << 4) + g;
        #pragma unroll
        for (int in = 0; in < 4; ++in) {
            int cl = (warp_s << 5) + (in << 3) + (tg << 1);
            float b0 = sbias[cl], b1 = sbias[cl + 1];
            float2 v0 = make_float2(acc[im][in][0] + b0, acc[im][in][1] + b1);
            float2 v1 = make_float2(acc[im][in][2] + b0, acc[im][in][3] + b1);
            *reinterpret_cast<float2*>(out + (size_t)r * S + s0 + cl)       = v0;
            *reinterpret_cast<float2*>(out + (size_t)(r + 8) * S + s0 + cl) = v1;
        }
    }
}

extern "C" void kernel_launch(void* const* d_in, const int* in_sizes, int n_in,
                              void* d_out, int out_size)
{
    const float*     x    = (const float*)d_in[0];
    const float*     w    = (const float*)d_in[1];
    const float*     bias = (const float*)d_in[2];
    const long long* ids  = (const long long*)d_in[3];
    float*           out  = (float*)d_out;

    const int rows = in_sizes[2];            // NUM_CLASS + 1
    const int D    = in_sizes[1] / rows;     // 512
    const int N    = in_sizes[0] / D;        // 256
    const int S    = in_sizes[3];            // 32768

    // Detect int32 vs int64 sample_ids (JAX x64-disabled emits int32).
    int nwords = S / 2;
    if (nwords > 4096) nwords = 4096;
    detect_ids_kernel<<<1, 256>>>(ids, nwords, (long long)rows);

    dim3 grid(S / BSAMP, N / BM);
    lsh_gemm_kernel<<<grid, 256>>>(x, w, bias, ids, out, N, D, S);
}

// round 2
// speedup vs baseline: 1.8280x; 1.8280x over previous
#include <cuda_runtime.h>
#include <cuda_bf16.h>
#include <stdint.h>

// C[N=256, S=32768] = x[N,512] @ gather(W, ids)[S,512]^T + bias[ids]
// fp32 accuracy via 3x bf16 split: x_hi*w_hi + x_lo*w_hi + x_hi*w_lo.
// CTA tile: 128(M) x 128(S). Per 32-wide K chunk we stage hi AND lo bf16
// tiles once, then run all 3 segments' MMAs from shared memory.
#define BM 128
#define BS 128
#define RS 20   // smem row stride in u32 (16 data + 4 pad -> conflict-free)

__device__ int g_ids32;  // 1 if sample_ids buffer is actually int32

__device__ __forceinline__ void cvt2(float f0, float f1, uint32_t& hi, uint32_t& lo) {
    __nv_bfloat162 h = __floats2bfloat162_rn(f0, f1);
    hi = *reinterpret_cast<uint32_t*>(&h);
    float r0 = f0 - __bfloat162float(__low2bfloat16(h));
    float r1 = f1 - __bfloat162float(__high2bfloat16(h));
    __nv_bfloat162 l = __floats2bfloat162_rn(r0, r1);
    lo = *reinterpret_cast<uint32_t*>(&l);
}

// Detect int64 vs int32 ids: int32 data misread as int64 yields out-of-range values.
__global__ void detect_ids_kernel(const long long* __restrict__ ids,
                                  int nwords, long long rows) {
    __shared__ int flag;
    if (threadIdx.x == 0) flag = 0;
    __syncthreads();
    for (int i = threadIdx.x; i < nwords; i += blockDim.x) {
        long long v = ids[i];
        if (v < 0 || v >= rows) flag = 1;
    }
    __syncthreads();
    if (threadIdx.x == 0) g_ids32 = flag;
}

__global__ __launch_bounds__(512)
void lsh_gemm_kernel(const float* __restrict__ x,
                     const float* __restrict__ w,
                     const float* __restrict__ bias,
                     const long long* __restrict__ ids,
                     float* __restrict__ out,
                     int N, int D, int S)
{
    __shared__ uint32_t sAh[BM * RS];
    __shared__ uint32_t sAl[BM * RS];
    __shared__ uint32_t sBh[BS * RS];
    __shared__ uint32_t sBl[BS * RS];
    __shared__ long long srow[BS];
    __shared__ float sbias[BS];

    const int tid = threadIdx.x;
    const int m0  = blockIdx.y * BM;
    const int s0  = blockIdx.x * BS;

    if (tid < BS) {
        int ids32 = g_ids32;
        long long gid = ids32 ? (long long)(((const int*)ids)[s0 + tid])
                              : ids[s0 + tid];
        srow[tid]  = gid * (long long)D;
        sbias[tid] = bias[gid];
    }

    const int lane   = tid & 31;
    const int wid    = tid >> 5;
    const int warp_m = wid >> 2;   // 0..3 -> 32 rows each
    const int warp_s = wid & 3;    // 0..3 -> 32 cols each
    const int g  = lane >> 2;      // 0..7
    const int tg = lane & 3;       // 0..3

    float acc[2][4][4];
    #pragma unroll
    for (int i = 0; i < 2; i++)
        #pragma unroll
        for (int j = 0; j < 4; j++)
            #pragma unroll
            for (int r = 0; r < 4; r++) acc[i][j][r] = 0.0f;

    __syncthreads();  // srow/sbias visible

    // Per-thread staging coordinates: 1024 float4 per tile (A and B), 2 each.
    int row0 = tid >> 3,            c40 = tid & 7;
    int row1 = (tid + 512) >> 3,    c41 = (tid + 512) & 7;
    const float* pa0 = x + (size_t)(m0 + row0) * D + (c40 << 2);
    const float* pa1 = x + (size_t)(m0 + row1) * D + (c41 << 2);
    const float* pb0 = w + srow[row0] + (c40 << 2);
    const float* pb1 = w + srow[row1] + (c41 << 2);

    const int nchunks = D >> 5;  // 16

    // Preload chunk 0
    float4 va0 = *reinterpret_cast<const float4*>(pa0);
    float4 va1 = *reinterpret_cast<const float4*>(pa1);
    float4 vb0 = *reinterpret_cast<const float4*>(pb0);
    float4 vb1 = *reinterpret_cast<const float4*>(pb1);

    for (int c = 0; c < nchunks; ++c) {
        if (c > 0) __syncthreads();  // prior MMA reads done before overwrite

        // Stage hi+lo conversions into smem
        {
            uint32_t h, l;
            cvt2(va0.x, va0.y, h, l);
            sAh[row0 * RS + (c40 << 1)] = h;  sAl[row0 * RS + (c40 << 1)] = l;
            cvt2(va0.z, va0.w, h, l);
            sAh[row0 * RS + (c40 << 1) + 1] = h;  sAl[row0 * RS + (c40 << 1) + 1] = l;
            cvt2(va1.x, va1.y, h, l);
            sAh[row1 * RS + (c41 << 1)] = h;  sAl[row1 * RS + (c41 << 1)] = l;
            cvt2(va1.z, va1.w, h, l);
            sAh[row1 * RS + (c41 << 1) + 1] = h;  sAl[row1 * RS + (c41 << 1) + 1] = l;
            cvt2(vb0.x, vb0.y, h, l);
            sBh[row0 * RS + (c40 << 1)] = h;  sBl[row0 * RS + (c40 << 1)] = l;
            cvt2(vb0.z, vb0.w, h, l);
            sBh[row0 * RS + (c40 << 1) + 1] = h;  sBl[row0 * RS + (c40 << 1) + 1] = l;
            cvt2(vb1.x, vb1.y, h, l);
            sBh[row1 * RS + (c41 << 1)] = h;  sBl[row1 * RS + (c41 << 1)] = l;
            cvt2(vb1.z, vb1.w, h, l);
            sBh[row1 * RS + (c41 << 1) + 1] = h;  sBl[row1 * RS + (c41 << 1) + 1] = l;
        }
        __syncthreads();

        // Prefetch next chunk (overlaps with MMA below)
        if (c + 1 < nchunks) {
            int k = (c + 1) << 5;
            va0 = *reinterpret_cast<const float4*>(pa0 + k);
            va1 = *reinterpret_cast<const float4*>(pa1 + k);
            vb0 = *reinterpret_cast<const float4*>(pb0 + k);
            vb1 = *reinterpret_cast<const float4*>(pb1 + k);
        }

        // 3 split segments from the same staged chunk
        #pragma unroll
        for (int seg = 0; seg < 3; ++seg) {
            const uint32_t* A = (seg == 1) ? sAl : sAh;
            const uint32_t* B = (seg == 2) ? sBl : sBh;
            #pragma unroll
            for (int ks = 0; ks < 2; ++ks) {
                uint32_t a[2][4];
                #pragma unroll
                for (int im = 0; im < 2; ++im) {
                    int base = ((warp_m << 5) + (im << 4) + g) * RS + (ks << 3) + tg;
                    a[im][0] = A[base];
                    a[im][1] = A[base + 8 * RS];
                    a[im][2] = A[base + 4];
                    a[im][3] = A[base + 8 * RS + 4];
                }
                uint32_t b[4][2];
                #pragma unroll
                for (int in = 0; in < 4; ++in) {
                    int base = ((warp_s << 5) + (in << 3) + g) * RS + (ks << 3) + tg;
                    b[in][0] = B[base];
                    b[in][1] = B[base + 4];
                }
                #pragma unroll
                for (int im = 0; im < 2; ++im)
                    #pragma unroll
                    for (int in = 0; in < 4; ++in) {
                        asm volatile(
                            "mma.sync.aligned.m16n8k16.row.col.f32.bf16.bf16.f32 "
                            "{%0,%1,%2,%3}, {%4,%5,%6,%7}, {%8,%9}, {%0,%1,%2,%3};\n"
                            : "+f"(acc[im][in][0]), "+f"(acc[im][in][1]),
                              "+f"(acc[im][in][2]), "+f"(acc[im][in][3])
                            : "r"(a[im][0]), "r"(a[im][1]),
                              "r"(a[im][2]), "r"(a[im][3]),
                              "r"(b[in][0]), "r"(b[in][1]));
                    }
            }
        }
    }

    // Epilogue: add bias, 64-bit stores
    #pragma unroll
    for (int im = 0; im < 2; ++im) {
        int r = m0 + (warp_m << 5) + (im << 4) + g;
        #pragma unroll
        for (int in = 0; in < 4; ++in) {
            int cl = (warp_s << 5) + (in << 3) + (tg << 1);
            float b0 = sbias[cl], b1 = sbias[cl + 1];
            float2 v0 = make_float2(acc[im][in][0] + b0, acc[im][in][1] + b1);
            float2 v1 = make_float2(acc[im][in][2] + b0, acc[im][in][3] + b1);
            *reinterpret_cast<float2*>(out + (size_t)r * S + s0 + cl)       = v0;
            *reinterpret_cast<float2*>(out + (size_t)(r + 8) * S + s0 + cl) = v1;
        }
    }
}

extern "C" void kernel_launch(void* const* d_in, const int* in_sizes, int n_in,
                              void* d_out, int out_size)
{
    const float*     x    = (const float*)d_in[0];
    const float*     w    = (const float*)d_in[1];
    const float*     bias = (const float*)d_in[2];
    const long long* ids  = (const long long*)d_in[3];
    float*           out  = (float*)d_out;

    const int rows = in_sizes[2];            // NUM_CLASS + 1
    const int D    = in_sizes[1] / rows;     // 512
    const int N    = in_sizes[0] / D;        // 256
    const int S    = in_sizes[3];            // 32768

    int nwords = S / 2;
    if (nwords > 4096) nwords = 4096;
    detect_ids_kernel<<<1, 256>>>(ids, nwords, (long long)rows);

    dim3 grid(S / BS, N / BM);
    lsh_gemm_kernel<<<grid, 512>>>(x, w, bias, ids, out, N, D, S);
}